// round 15
// baseline (speedup 1.0000x reference)
#include <cuda_runtime.h>
#include <cuda_bf16.h>
#include <math.h>

#define VOCAB 50257
#define DIM   128
#define HID   128
#define GATES 512
#define BATCH 64
#define SEQ   2048

typedef unsigned long long ull;

// Projected embedding table: P[v][g] = dot(emb[v], W_ih[g]) + b_ih[g] + b_hh[g]
__device__ float g_P[(size_t)VOCAB * GATES];
// bf16 hi/lo splits (precomputed once)
__device__ __nv_bfloat16 g_ehi[(size_t)VOCAB * DIM];
__device__ __nv_bfloat16 g_elo[(size_t)VOCAB * DIM];
__device__ __nv_bfloat16 g_whi[(size_t)GATES * DIM];
__device__ __nv_bfloat16 g_wlo[(size_t)GATES * DIM];
__device__ float g_bias[GATES];

#define FMA2(acc, a, b) \
    asm("fma.rn.f32x2 %0, %1, %2, %0;" : "+l"(acc) : "l"(a), "l"(b))

__device__ __forceinline__ unsigned cvta_smem_u32(const void* p) {
    unsigned r;
    asm("{ .reg .u64 t; cvta.to.shared.u64 t, %1; cvt.u32.u64 %0, t; }"
        : "=r"(r) : "l"(p));
    return r;
}
__device__ __forceinline__ unsigned pack_hi(float a, float b) {
    __nv_bfloat162 v = __float22bfloat162_rn(make_float2(a, b));
    return *reinterpret_cast<unsigned*>(&v);
}

// ===========================================================================
// Kernel 0: one-shot bf16 hi/lo split of emb and W_ih, + fused bias.
// ===========================================================================
#define NE4 ((VOCAB * DIM) / 4)     // 1608224 float4 groups
#define NW4 ((GATES * DIM) / 4)     // 16384

__global__ __launch_bounds__(256) void split_kernel(
    const float* __restrict__ emb,
    const float* __restrict__ W_ih,
    const float* __restrict__ b_ih,
    const float* __restrict__ b_hh)
{
    const int i = blockIdx.x * 256 + threadIdx.x;
    if (i < NE4) {
        float4 v = ((const float4*)emb)[i];
        unsigned h0 = pack_hi(v.x, v.y), h1 = pack_hi(v.z, v.w);
        __nv_bfloat162 hb0 = *reinterpret_cast<__nv_bfloat162*>(&h0);
        __nv_bfloat162 hb1 = *reinterpret_cast<__nv_bfloat162*>(&h1);
        unsigned l0 = pack_hi(v.x - __bfloat162float(hb0.x),
                              v.y - __bfloat162float(hb0.y));
        unsigned l1 = pack_hi(v.z - __bfloat162float(hb1.x),
                              v.w - __bfloat162float(hb1.y));
        ((uint2*)g_ehi)[i] = make_uint2(h0, h1);
        ((uint2*)g_elo)[i] = make_uint2(l0, l1);
    } else if (i < NE4 + NW4) {
        const int j = i - NE4;
        float4 v = ((const float4*)W_ih)[j];
        unsigned h0 = pack_hi(v.x, v.y), h1 = pack_hi(v.z, v.w);
        __nv_bfloat162 hb0 = *reinterpret_cast<__nv_bfloat162*>(&h0);
        __nv_bfloat162 hb1 = *reinterpret_cast<__nv_bfloat162*>(&h1);
        unsigned l0 = pack_hi(v.x - __bfloat162float(hb0.x),
                              v.y - __bfloat162float(hb0.y));
        unsigned l1 = pack_hi(v.z - __bfloat162float(hb1.x),
                              v.w - __bfloat162float(hb1.y));
        ((uint2*)g_whi)[j] = make_uint2(h0, h1);
        ((uint2*)g_wlo)[j] = make_uint2(l0, l1);
    } else if (i < NE4 + NW4 + GATES) {
        const int j = i - NE4 - NW4;
        g_bias[j] = b_ih[j] + b_hh[j];
    }
}

// ===========================================================================
// Kernel 1: P = emb @ W_ih^T + b via HMMA, 128x64x128 tiles, bf16 3-term.
//   Tile shrunk N=128 -> 64: smem 139.8 KB -> ~102 KB -> 2 CTAs/SM, so one
//   CTA's global-load prologue overlaps the other's MMA phase.
//   256 thr / 8 warps; warp tile m32 x n32. Rows padded to 272 B.
// ===========================================================================
#define PROWB 272                       // bytes per padded smem row
#define T_AHI 0
#define T_ALO (T_AHI + 128 * PROWB)     // A: 128 rows
#define T_BHI (T_ALO + 128 * PROWB)     // B: 64 rows
#define T_BLO (T_BHI + 64 * PROWB)
#define T_BIAS (T_BLO + 64 * PROWB)
#define SM_PROJ (T_BIAS + 64 * 4)       // 104704 B

#define LDSM4(R, ADDR)                                                      \
    asm volatile("ldmatrix.sync.aligned.m8n8.x4.shared.b16 "                \
                 "{%0,%1,%2,%3}, [%4];"                                     \
                 : "=r"((R)[0]), "=r"((R)[1]), "=r"((R)[2]), "=r"((R)[3])   \
                 : "r"(ADDR))

#define MMA16816(D, A, B0, B1)                                              \
    asm volatile("mma.sync.aligned.m16n8k16.row.col.f32.bf16.bf16.f32 "     \
                 "{%0,%1,%2,%3}, {%4,%5,%6,%7}, {%8,%9}, {%0,%1,%2,%3};"    \
                 : "+f"((D)[0]), "+f"((D)[1]), "+f"((D)[2]), "+f"((D)[3])   \
                 : "r"((A)[0]), "r"((A)[1]), "r"((A)[2]), "r"((A)[3]),      \
                   "r"(B0), "r"(B1))

__global__ __launch_bounds__(256) void proj_mma_kernel(void)
{
    extern __shared__ __align__(16) unsigned char sm[];
    const unsigned base = cvta_smem_u32(sm);

    const int tid = threadIdx.x;
    const int m0  = blockIdx.x << 7;
    const int n0  = blockIdx.y << 6;

    // ---- load A tiles: thread t -> row t>>1, half-row (t&1)*128 bytes ----
    {
        const int r    = tid >> 1;
        const int half = tid & 1;
        const int gm   = m0 + r;
        const bool av  = (gm < VOCAB);
        const uint4 z  = make_uint4(0u, 0u, 0u, 0u);

        const size_t aoff = ((size_t)(av ? gm : 0) * DIM + half * 64) * 2;
        const uint4* ah = (const uint4*)((const char*)g_ehi + aoff);
        const uint4* al = (const uint4*)((const char*)g_elo + aoff);
        unsigned char* dA  = sm + T_AHI + r * PROWB + half * 128;
        unsigned char* dAl = sm + T_ALO + r * PROWB + half * 128;
        #pragma unroll
        for (int q = 0; q < 8; ++q) {
            *(uint4*)(dA  + 16 * q) = av ? ah[q] : z;
            *(uint4*)(dAl + 16 * q) = av ? al[q] : z;
        }
    }
    // ---- load B tiles (64 rows): thread t -> row t>>2, quarter (t&3)*64 B --
    {
        const int r = tid >> 2;
        const int qtr = tid & 3;
        const size_t boff = ((size_t)(n0 + r) * DIM + qtr * 32) * 2;
        const uint4* bh = (const uint4*)((const char*)g_whi + boff);
        const uint4* bl = (const uint4*)((const char*)g_wlo + boff);
        unsigned char* dB  = sm + T_BHI + r * PROWB + qtr * 64;
        unsigned char* dBl = sm + T_BLO + r * PROWB + qtr * 64;
        #pragma unroll
        for (int q = 0; q < 4; ++q) {
            *(uint4*)(dB  + 16 * q) = bh[q];
            *(uint4*)(dBl + 16 * q) = bl[q];
        }
        if (tid < 64)
            ((float*)(sm + T_BIAS))[tid] = g_bias[n0 + tid];
    }
    __syncthreads();

    // ---- mma: warp w -> m strip (w&3)*32, n strip (w>>2)*32 ----
    const int w    = tid >> 5;
    const int lane = tid & 31;
    const int ms   = (w & 3) << 5;
    const int ns   = (w >> 2) << 5;

    float acc[2][4][4];
    #pragma unroll
    for (int mi = 0; mi < 2; ++mi)
        #pragma unroll
        for (int nt = 0; nt < 4; ++nt)
            #pragma unroll
            for (int i = 0; i < 4; ++i) acc[mi][nt][i] = 0.f;

    const int a_row = ms + (lane & 15);
    const int a_k   = (lane & 16) ? 16 : 0;
    const int b_row = ns + (lane & 7) + ((lane & 16) ? 8 : 0);
    const int b_k   = (lane & 8) ? 16 : 0;

    const unsigned A0h = base + T_AHI + a_row * PROWB + a_k;
    const unsigned A1h = A0h + 16 * PROWB;
    const unsigned A0l = base + T_ALO + a_row * PROWB + a_k;
    const unsigned A1l = A0l + 16 * PROWB;
    const unsigned Bh0 = base + T_BHI + b_row * PROWB + b_k;
    const unsigned Bl0 = base + T_BLO + b_row * PROWB + b_k;

    #pragma unroll
    for (int s = 0; s < 8; ++s) {
        const unsigned ko = s * 32;
        unsigned ah[2][4], al[2][4], bh[2][4], bl[2][4];
        LDSM4(ah[0], A0h + ko);
        LDSM4(ah[1], A1h + ko);
        LDSM4(al[0], A0l + ko);
        LDSM4(al[1], A1l + ko);
        #pragma unroll
        for (int q = 0; q < 2; ++q) {
            LDSM4(bh[q], Bh0 + q * 16 * PROWB + ko);
            LDSM4(bl[q], Bl0 + q * 16 * PROWB + ko);
        }
        #pragma unroll
        for (int mi = 0; mi < 2; ++mi) {
            #pragma unroll
            for (int q = 0; q < 2; ++q) {
                #pragma unroll
                for (int jn = 0; jn < 2; ++jn) {
                    const int nt = 2 * q + jn;
                    MMA16816(acc[mi][nt], ah[mi], bh[q][2 * jn], bh[q][2 * jn + 1]);
                    MMA16816(acc[mi][nt], ah[mi], bl[q][2 * jn], bl[q][2 * jn + 1]);
                    MMA16816(acc[mi][nt], al[mi], bh[q][2 * jn], bh[q][2 * jn + 1]);
                }
            }
        }
    }

    // ---- epilogue ----
    {
        const float* bias = (const float*)(sm + T_BIAS);
        #pragma unroll
        for (int mi = 0; mi < 2; ++mi) {
            const int row0 = m0 + ms + mi * 16 + (lane >> 2);
            const int row1 = row0 + 8;
            #pragma unroll
            for (int nt = 0; nt < 4; ++nt) {
                const int cl = ns + ((lane & 3) << 1) + nt * 8;
                const float b0 = bias[cl], b1 = bias[cl + 1];
                if (row0 < VOCAB)
                    *(float2*)(g_P + (size_t)row0 * GATES + n0 + cl) =
                        make_float2(acc[mi][nt][0] + b0, acc[mi][nt][1] + b1);
                if (row1 < VOCAB)
                    *(float2*)(g_P + (size_t)row1 * GATES + n0 + cl) =
                        make_float2(acc[mi][nt][2] + b0, acc[mi][nt][3] + b1);
            }
        }
    }
}

// ===========================================================================
// Kernel 2: recurrent LSTM — R14 skeleton (per-warp mbarriers); changes:
//   (a) a_s interleaved [unit*4+gate] -> tail does ONE LDS.128
//   (b) #pragma unroll 2 on the t loop
// ===========================================================================
__device__ __forceinline__ float tanh_hw(float x) {
    float r;
    asm("tanh.approx.f32 %0, %1;" : "=f"(r) : "f"(x));
    return r;
}
__device__ __forceinline__ unsigned cvta_smem(const void* p) {
    unsigned r;
    asm("{ .reg .u64 t; cvta.to.shared.u64 t, %1; cvt.u32.u64 %0, t; }"
        : "=r"(r) : "l"(p));
    return r;
}

#define MBWAIT(addr, par) do {                                                 \
    unsigned _done;                                                            \
    asm volatile(                                                              \
        "{\n\t.reg .pred p;\n\t"                                               \
        "mbarrier.try_wait.parity.acquire.cta.shared::cta.b64 p, [%1], %2;\n\t" \
        "selp.b32 %0, 1, 0, p;\n\t}"                                           \
        : "=r"(_done) : "r"(addr), "r"(par) : "memory");                       \
    if (!_done) {                                                              \
        asm volatile(                                                          \
            "{\n\t.reg .pred P1;\n\t"                                          \
            "WL_%=:\n\t"                                                       \
            "mbarrier.try_wait.parity.acquire.cta.shared::cta.b64 P1, [%0], %1, 0x989680;\n\t" \
            "@P1 bra.uni WD_%=;\n\t"                                           \
            "bra.uni WL_%=;\n\t"                                               \
            "WD_%=:\n\t}"                                                      \
            :: "r"(addr), "r"(par) : "memory");                                \
    }                                                                          \
} while (0)

__global__ __launch_bounds__(512, 1) __cluster_dims__(2, 1, 1)
void lstm_kernel(
    const int*   __restrict__ tokens,
    const float* __restrict__ W_hh,
    float*       __restrict__ out)
{
    __shared__ __align__(16) ull   mbar[16];       // one per warp
    __shared__ __align__(16) float h_s[128];
    __shared__ __align__(16) float a_s[512];       // [unit*4 + gate]
    __shared__ __align__(16) float pbuf[2][512];   // peer partials, double buffered
    __shared__ int tok_s[SEQ];

    const int j    = threadIdx.x;
    const int w    = j >> 5;
    const int lane = j & 31;
    const int b    = blockIdx.x >> 1;
    const int rank = blockIdx.x & 1;
    const int peer = rank ^ 1;

    const ull* W64 = (const ull*)W_hh;

    ull wreg[32];
    #pragma unroll
    for (int kk = 0; kk < 32; ++kk)
        wreg[kk] = W64[(size_t)j * 64 + (rank << 5) + kk];

    if (rank == 0) {
        for (int idx = j; idx < SEQ; idx += 512)
            tok_s[idx] = tokens[(size_t)b * SEQ + idx];
    }
    if (j < 128) h_s[j] = 0.f;

    const unsigned mbar_a = cvta_smem(mbar);
    const unsigned pbuf_a = cvta_smem(pbuf);
    if (j < 16) {
        asm volatile("mbarrier.init.shared.b64 [%0], %1;"
                     :: "r"(mbar_a + (unsigned)(j << 3)), "r"(1u) : "memory");
    }
    __syncthreads();
    asm volatile("barrier.cluster.arrive.aligned;" ::: "memory");
    asm volatile("barrier.cluster.wait.aligned;"   ::: "memory");

    unsigned rm_mbar, rm_pbuf;
    asm("mapa.shared::cluster.u32 %0, %1, %2;" : "=r"(rm_mbar) : "r"(mbar_a), "r"(peer));
    asm("mapa.shared::cluster.u32 %0, %1, %2;" : "=r"(rm_pbuf) : "r"(pbuf_a), "r"(peer));

    const float* Pp = (const float*)g_P;
    float x_cur = (rank == 0) ? __ldg(Pp + (size_t)tok_s[0] * GATES + j) : 0.f;
    float c = 0.f;
    const bool sel_tanh = ((j >> 7) == 2);   // gate order i, f, g(tanh), o
    const int  aidx = ((j & 127) << 2) + (j >> 7);   // interleaved a_s slot
    const ulonglong2* h2 = (const ulonglong2*)(h_s + (rank << 6));
    const unsigned my_mbar = mbar_a + (unsigned)(w << 3);   // my warp's barrier

    #pragma unroll 2
    for (int t = 0; t < SEQ; ++t) {
        if (lane == 0) {   // arm my warp's barrier: 1 arrival + 128 tx bytes
            asm volatile("mbarrier.arrive.expect_tx.shared.b64 _, [%0], %1;"
                         :: "r"(my_mbar), "r"(128u) : "memory");
        }

        float xg = x_cur;
        if (rank == 0 && t + 1 < SEQ)
            x_cur = __ldg(Pp + (size_t)tok_s[t + 1] * GATES + j);

        ull a0 = 0ull, a1 = 0ull, a2 = 0ull, a3 = 0ull;
        #pragma unroll
        for (int q = 0; q < 8; ++q) {
            ulonglong2 ha = h2[2 * q];
            ulonglong2 hb = h2[2 * q + 1];
            FMA2(a0, wreg[4 * q + 0], ha.x);
            FMA2(a1, wreg[4 * q + 1], ha.y);
            FMA2(a2, wreg[4 * q + 2], hb.x);
            FMA2(a3, wreg[4 * q + 3], hb.y);
        }
        float s0, s1, s2, s3, s4, s5, s6, s7;
        asm("mov.b64 {%0,%1}, %2;" : "=f"(s0), "=f"(s1) : "l"(a0));
        asm("mov.b64 {%0,%1}, %2;" : "=f"(s2), "=f"(s3) : "l"(a1));
        asm("mov.b64 {%0,%1}, %2;" : "=f"(s4), "=f"(s5) : "l"(a2));
        asm("mov.b64 {%0,%1}, %2;" : "=f"(s6), "=f"(s7) : "l"(a3));
        float part = ((s0 + s1) + (s2 + s3)) + ((s4 + s5) + (s6 + s7));
        if (rank == 0) part += xg;

        {   // pack 2 partials -> b64 message to peer's warp-w mbar
            float pnext = __shfl_down_sync(0xFFFFFFFFu, part, 1);
            if ((j & 1) == 0) {
                ull pk;
                asm("mov.b64 %0, {%1,%2};" : "=l"(pk) : "f"(part), "f"(pnext));
                unsigned dst = rm_pbuf + (((unsigned)(t & 1) << 9) + j) * 4u;
                asm volatile(
                    "st.async.shared::cluster.mbarrier::complete_tx::bytes.b64 [%0], %1, [%2];"
                    :: "r"(dst), "l"(pk), "r"(rm_mbar + (unsigned)(w << 3)) : "memory");
            }
        }

        MBWAIT(my_mbar, (unsigned)(t & 1));   // wait only for my warp's 128 B

        float g = part + pbuf[t & 1][j];
        float targ = sel_tanh ? g : 0.5f * g;
        float th   = tanh_hw(targ);
        float act  = sel_tanh ? th : fmaf(0.5f, th, 0.5f);
        a_s[aidx] = act;
        __syncthreads();

        if (j < 128) {
            float4 av = *(const float4*)&a_s[j << 2];   // i,f,g,o of unit j
            c = fmaf(av.y, c, av.x * av.z);
            h_s[j] = av.w * tanh_hw(c);
        }
        __syncthreads();
    }

    if (rank == 0 && j < 128) {
        out[(size_t)b * HID + j] = h_s[j];                        // h  [1,64,128]
        out[(size_t)BATCH * HID + (size_t)b * HID + j] = c;       // c  [1,64,128]
    }

    asm volatile("barrier.cluster.arrive.aligned;" ::: "memory");
    asm volatile("barrier.cluster.wait.aligned;"   ::: "memory");
}

// ---------------------------------------------------------------------------
extern "C" void kernel_launch(void* const* d_in, const int* in_sizes, int n_in,
                              void* d_out, int out_size)
{
    const int*   tokens = (const int*)  d_in[0];
    const float* emb    = (const float*)d_in[1];
    const float* W_ih   = (const float*)d_in[2];
    const float* W_hh   = (const float*)d_in[3];
    const float* b_ih   = (const float*)d_in[4];
    const float* b_hh   = (const float*)d_in[5];
    float* out = (float*)d_out;

    cudaFuncSetAttribute(proj_mma_kernel,
                         cudaFuncAttributeMaxDynamicSharedMemorySize, SM_PROJ);

    const int ntot = NE4 + NW4 + GATES;
    split_kernel<<<(ntot + 255) / 256, 256>>>(emb, W_ih, b_ih, b_hh);

    dim3 g1((VOCAB + 127) / 128, GATES / 64);   // 393 x 8
    proj_mma_kernel<<<g1, 256, SM_PROJ>>>();

    lstm_kernel<<<BATCH * 2, 512>>>(tokens, W_hh, out);
}

// round 16
// speedup vs baseline: 1.6407x; 1.6407x over previous
#include <cuda_runtime.h>
#include <cuda_bf16.h>
#include <math.h>

#define VOCAB 50257
#define DIM   128
#define HID   128
#define GATES 512
#define BATCH 64
#define SEQ   2048

typedef unsigned long long ull;

// Projected embedding table: P[v][g] = dot(emb[v], W_ih[g]) + b_ih[g] + b_hh[g]
__device__ float g_P[(size_t)VOCAB * GATES];
// bf16 hi/lo splits (precomputed once)
__device__ __nv_bfloat16 g_ehi[(size_t)VOCAB * DIM];
__device__ __nv_bfloat16 g_elo[(size_t)VOCAB * DIM];
__device__ __nv_bfloat16 g_whi[(size_t)GATES * DIM];
__device__ __nv_bfloat16 g_wlo[(size_t)GATES * DIM];
__device__ float g_bias[GATES];

#define FMA2(acc, a, b) \
    asm("fma.rn.f32x2 %0, %1, %2, %0;" : "+l"(acc) : "l"(a), "l"(b))
#define ADD2(out, a, b) \
    asm("add.rn.f32x2 %0, %1, %2;" : "=l"(out) : "l"(a), "l"(b))

__device__ __forceinline__ unsigned cvta_smem_u32(const void* p) {
    unsigned r;
    asm("{ .reg .u64 t; cvta.to.shared.u64 t, %1; cvt.u32.u64 %0, t; }"
        : "=r"(r) : "l"(p));
    return r;
}
__device__ __forceinline__ unsigned pack_hi(float a, float b) {
    __nv_bfloat162 v = __float22bfloat162_rn(make_float2(a, b));
    return *reinterpret_cast<unsigned*>(&v);
}

// ===========================================================================
// Kernel 0: one-shot bf16 hi/lo split of emb and W_ih, + fused bias.
// ===========================================================================
#define NE4 ((VOCAB * DIM) / 4)     // 1608224 float4 groups
#define NW4 ((GATES * DIM) / 4)     // 16384

__global__ __launch_bounds__(256) void split_kernel(
    const float* __restrict__ emb,
    const float* __restrict__ W_ih,
    const float* __restrict__ b_ih,
    const float* __restrict__ b_hh)
{
    const int i = blockIdx.x * 256 + threadIdx.x;
    if (i < NE4) {
        float4 v = ((const float4*)emb)[i];
        unsigned h0 = pack_hi(v.x, v.y), h1 = pack_hi(v.z, v.w);
        __nv_bfloat162 hb0 = *reinterpret_cast<__nv_bfloat162*>(&h0);
        __nv_bfloat162 hb1 = *reinterpret_cast<__nv_bfloat162*>(&h1);
        unsigned l0 = pack_hi(v.x - __bfloat162float(hb0.x),
                              v.y - __bfloat162float(hb0.y));
        unsigned l1 = pack_hi(v.z - __bfloat162float(hb1.x),
                              v.w - __bfloat162float(hb1.y));
        ((uint2*)g_ehi)[i] = make_uint2(h0, h1);
        ((uint2*)g_elo)[i] = make_uint2(l0, l1);
    } else if (i < NE4 + NW4) {
        const int j = i - NE4;
        float4 v = ((const float4*)W_ih)[j];
        unsigned h0 = pack_hi(v.x, v.y), h1 = pack_hi(v.z, v.w);
        __nv_bfloat162 hb0 = *reinterpret_cast<__nv_bfloat162*>(&h0);
        __nv_bfloat162 hb1 = *reinterpret_cast<__nv_bfloat162*>(&h1);
        unsigned l0 = pack_hi(v.x - __bfloat162float(hb0.x),
                              v.y - __bfloat162float(hb0.y));
        unsigned l1 = pack_hi(v.z - __bfloat162float(hb1.x),
                              v.w - __bfloat162float(hb1.y));
        ((uint2*)g_whi)[j] = make_uint2(h0, h1);
        ((uint2*)g_wlo)[j] = make_uint2(l0, l1);
    } else if (i < NE4 + NW4 + GATES) {
        const int j = i - NE4 - NW4;
        g_bias[j] = b_ih[j] + b_hh[j];
    }
}

// ===========================================================================
// Kernel 1: P = emb @ W_ih^T + b via HMMA, 128x128x128 tiles, bf16 3-term.
//   (R14 configuration — measured best)
// ===========================================================================
#define PROWB 272                       // bytes per padded smem row
#define T_AHI 0
#define T_ALO (T_AHI + 128 * PROWB)
#define T_BHI (T_ALO + 128 * PROWB)
#define T_BLO (T_BHI + 128 * PROWB)
#define T_BIAS (T_BLO + 128 * PROWB)
#define SM_PROJ (T_BIAS + 128 * 4)      // 139776 B

#define LDSM4(R, ADDR)                                                      \
    asm volatile("ldmatrix.sync.aligned.m8n8.x4.shared.b16 "                \
                 "{%0,%1,%2,%3}, [%4];"                                     \
                 : "=r"((R)[0]), "=r"((R)[1]), "=r"((R)[2]), "=r"((R)[3])   \
                 : "r"(ADDR))

#define MMA16816(D, A, B0, B1)                                              \
    asm volatile("mma.sync.aligned.m16n8k16.row.col.f32.bf16.bf16.f32 "     \
                 "{%0,%1,%2,%3}, {%4,%5,%6,%7}, {%8,%9}, {%0,%1,%2,%3};"    \
                 : "+f"((D)[0]), "+f"((D)[1]), "+f"((D)[2]), "+f"((D)[3])   \
                 : "r"((A)[0]), "r"((A)[1]), "r"((A)[2]), "r"((A)[3]),      \
                   "r"(B0), "r"(B1))

__global__ __launch_bounds__(256) void proj_mma_kernel(void)
{
    extern __shared__ __align__(16) unsigned char sm[];
    const unsigned base = cvta_smem_u32(sm);

    const int tid = threadIdx.x;
    const int m0  = blockIdx.x << 7;
    const int n0  = blockIdx.y << 7;

    // ---- load tiles: thread t -> row t>>1, half-row (t&1)*128 bytes ----
    {
        const int r    = tid >> 1;
        const int half = tid & 1;
        const int gm   = m0 + r;
        const bool av  = (gm < VOCAB);
        const uint4 z  = make_uint4(0u, 0u, 0u, 0u);

        const size_t aoff = ((size_t)(av ? gm : 0) * DIM + half * 64) * 2;
        const uint4* ah = (const uint4*)((const char*)g_ehi + aoff);
        const uint4* al = (const uint4*)((const char*)g_elo + aoff);
        const size_t boff = ((size_t)(n0 + r) * DIM + half * 64) * 2;
        const uint4* bh = (const uint4*)((const char*)g_whi + boff);
        const uint4* bl = (const uint4*)((const char*)g_wlo + boff);

        unsigned char* dA  = sm + T_AHI + r * PROWB + half * 128;
        unsigned char* dAl = sm + T_ALO + r * PROWB + half * 128;
        unsigned char* dB  = sm + T_BHI + r * PROWB + half * 128;
        unsigned char* dBl = sm + T_BLO + r * PROWB + half * 128;

        #pragma unroll
        for (int q = 0; q < 8; ++q) {
            *(uint4*)(dA  + 16 * q) = av ? ah[q] : z;
            *(uint4*)(dAl + 16 * q) = av ? al[q] : z;
            *(uint4*)(dB  + 16 * q) = bh[q];
            *(uint4*)(dBl + 16 * q) = bl[q];
        }

        if (tid < 128)
            ((float*)(sm + T_BIAS))[tid] = g_bias[n0 + tid];
    }
    __syncthreads();

    // ---- mma: warp w -> m strip (w&3)*32, n strip (w>>2)*64 ----
    const int w    = tid >> 5;
    const int lane = tid & 31;
    const int ms   = (w & 3) << 5;
    const int ns   = (w >> 2) << 6;

    float acc[2][8][4];
    #pragma unroll
    for (int mi = 0; mi < 2; ++mi)
        #pragma unroll
        for (int nt = 0; nt < 8; ++nt)
            #pragma unroll
            for (int i = 0; i < 4; ++i) acc[mi][nt][i] = 0.f;

    const int a_row = ms + (lane & 15);
    const int a_k   = (lane & 16) ? 16 : 0;
    const int b_row = ns + (lane & 7) + ((lane & 16) ? 8 : 0);
    const int b_k   = (lane & 8) ? 16 : 0;

    const unsigned A0h = base + T_AHI + a_row * PROWB + a_k;
    const unsigned A1h = A0h + 16 * PROWB;
    const unsigned A0l = base + T_ALO + a_row * PROWB + a_k;
    const unsigned A1l = A0l + 16 * PROWB;
    const unsigned Bh0 = base + T_BHI + b_row * PROWB + b_k;
    const unsigned Bl0 = base + T_BLO + b_row * PROWB + b_k;

    #pragma unroll
    for (int s = 0; s < 8; ++s) {
        const unsigned ko = s * 32;
        unsigned ah[2][4], al[2][4], bh[4][4], bl[4][4];
        LDSM4(ah[0], A0h + ko);
        LDSM4(ah[1], A1h + ko);
        LDSM4(al[0], A0l + ko);
        LDSM4(al[1], A1l + ko);
        #pragma unroll
        for (int q = 0; q < 4; ++q) {
            LDSM4(bh[q], Bh0 + q * 16 * PROWB + ko);
            LDSM4(bl[q], Bl0 + q * 16 * PROWB + ko);
        }
        #pragma unroll
        for (int mi = 0; mi < 2; ++mi) {
            #pragma unroll
            for (int q = 0; q < 4; ++q) {
                #pragma unroll
                for (int jn = 0; jn < 2; ++jn) {
                    const int nt = 2 * q + jn;
                    MMA16816(acc[mi][nt], ah[mi], bh[q][2 * jn], bh[q][2 * jn + 1]);
                    MMA16816(acc[mi][nt], ah[mi], bl[q][2 * jn], bl[q][2 * jn + 1]);
                    MMA16816(acc[mi][nt], al[mi], bh[q][2 * jn], bh[q][2 * jn + 1]);
                }
            }
        }
    }

    // ---- epilogue ----
    {
        const float* bias = (const float*)(sm + T_BIAS);
        #pragma unroll
        for (int mi = 0; mi < 2; ++mi) {
            const int row0 = m0 + ms + mi * 16 + (lane >> 2);
            const int row1 = row0 + 8;
            #pragma unroll
            for (int nt = 0; nt < 8; ++nt) {
                const int cl = ns + ((lane & 3) << 1) + nt * 8;
                const float b0 = bias[cl], b1 = bias[cl + 1];
                if (row0 < VOCAB)
                    *(float2*)(g_P + (size_t)row0 * GATES + n0 + cl) =
                        make_float2(acc[mi][nt][0] + b0, acc[mi][nt][1] + b1);
                if (row1 < VOCAB)
                    *(float2*)(g_P + (size_t)row1 * GATES + n0 + cl) =
                        make_float2(acc[mi][nt][2] + b0, acc[mi][nt][3] + b1);
            }
        }
    }
}

// ===========================================================================
// Kernel 2: recurrent LSTM — R14 skeleton (per-warp mbarriers); ONLY change:
// packed f32x2 accumulator reduction (5 instrs vs 11).
// ===========================================================================
__device__ __forceinline__ float tanh_hw(float x) {
    float r;
    asm("tanh.approx.f32 %0, %1;" : "=f"(r) : "f"(x));
    return r;
}
__device__ __forceinline__ unsigned cvta_smem(const void* p) {
    unsigned r;
    asm("{ .reg .u64 t; cvta.to.shared.u64 t, %1; cvt.u32.u64 %0, t; }"
        : "=r"(r) : "l"(p));
    return r;
}

#define MBWAIT(addr, par) do {                                                 \
    unsigned _done;                                                            \
    asm volatile(                                                              \
        "{\n\t.reg .pred p;\n\t"                                               \
        "mbarrier.try_wait.parity.acquire.cta.shared::cta.b64 p, [%1], %2;\n\t" \
        "selp.b32 %0, 1, 0, p;\n\t}"                                           \
        : "=r"(_done) : "r"(addr), "r"(par) : "memory");                       \
    if (!_done) {                                                              \
        asm volatile(                                                          \
            "{\n\t.reg .pred P1;\n\t"                                          \
            "WL_%=:\n\t"                                                       \
            "mbarrier.try_wait.parity.acquire.cta.shared::cta.b64 P1, [%0], %1, 0x989680;\n\t" \
            "@P1 bra.uni WD_%=;\n\t"                                           \
            "bra.uni WL_%=;\n\t"                                               \
            "WD_%=:\n\t}"                                                      \
            :: "r"(addr), "r"(par) : "memory");                                \
    }                                                                          \
} while (0)

__global__ __launch_bounds__(512, 1) __cluster_dims__(2, 1, 1)
void lstm_kernel(
    const int*   __restrict__ tokens,
    const float* __restrict__ W_hh,
    float*       __restrict__ out)
{
    __shared__ __align__(16) ull   mbar[16];       // one per warp
    __shared__ __align__(16) float h_s[128];
    __shared__ __align__(16) float a_s[512];
    __shared__ __align__(16) float pbuf[2][512];   // peer partials, double buffered
    __shared__ int tok_s[SEQ];

    const int j    = threadIdx.x;
    const int w    = j >> 5;
    const int lane = j & 31;
    const int b    = blockIdx.x >> 1;
    const int rank = blockIdx.x & 1;
    const int peer = rank ^ 1;

    const ull* W64 = (const ull*)W_hh;

    ull wreg[32];
    #pragma unroll
    for (int kk = 0; kk < 32; ++kk)
        wreg[kk] = W64[(size_t)j * 64 + (rank << 5) + kk];

    if (rank == 0) {
        for (int idx = j; idx < SEQ; idx += 512)
            tok_s[idx] = tokens[(size_t)b * SEQ + idx];
    }
    if (j < 128) h_s[j] = 0.f;

    const unsigned mbar_a = cvta_smem(mbar);
    const unsigned pbuf_a = cvta_smem(pbuf);
    if (j < 16) {
        asm volatile("mbarrier.init.shared.b64 [%0], %1;"
                     :: "r"(mbar_a + (unsigned)(j << 3)), "r"(1u) : "memory");
    }
    __syncthreads();
    asm volatile("barrier.cluster.arrive.aligned;" ::: "memory");
    asm volatile("barrier.cluster.wait.aligned;"   ::: "memory");

    unsigned rm_mbar, rm_pbuf;
    asm("mapa.shared::cluster.u32 %0, %1, %2;" : "=r"(rm_mbar) : "r"(mbar_a), "r"(peer));
    asm("mapa.shared::cluster.u32 %0, %1, %2;" : "=r"(rm_pbuf) : "r"(pbuf_a), "r"(peer));

    const float* Pp = (const float*)g_P;
    float x_cur = (rank == 0) ? __ldg(Pp + (size_t)tok_s[0] * GATES + j) : 0.f;
    float c = 0.f;
    const bool sel_tanh = ((j >> 7) == 2);   // gate order i, f, g(tanh), o
    const ulonglong2* h2 = (const ulonglong2*)(h_s + (rank << 6));
    const unsigned my_mbar = mbar_a + (unsigned)(w << 3);   // my warp's barrier

    for (int t = 0; t < SEQ; ++t) {
        if (lane == 0) {   // arm my warp's barrier: 1 arrival + 128 tx bytes
            asm volatile("mbarrier.arrive.expect_tx.shared.b64 _, [%0], %1;"
                         :: "r"(my_mbar), "r"(128u) : "memory");
        }

        float xg = x_cur;
        if (rank == 0 && t + 1 < SEQ)
            x_cur = __ldg(Pp + (size_t)tok_s[t + 1] * GATES + j);

        ull a0 = 0ull, a1 = 0ull, a2 = 0ull, a3 = 0ull;
        #pragma unroll
        for (int q = 0; q < 8; ++q) {
            ulonglong2 ha = h2[2 * q];
            ulonglong2 hb = h2[2 * q + 1];
            FMA2(a0, wreg[4 * q + 0], ha.x);
            FMA2(a1, wreg[4 * q + 1], ha.y);
            FMA2(a2, wreg[4 * q + 2], hb.x);
            FMA2(a3, wreg[4 * q + 3], hb.y);
        }
        // packed f32x2 tree reduction: 3 packed adds + 1 unpack + 1 add
        ull a01, a23, at;
        ADD2(a01, a0, a1);
        ADD2(a23, a2, a3);
        ADD2(at, a01, a23);
        float tlo, thi;
        asm("mov.b64 {%0,%1}, %2;" : "=f"(tlo), "=f"(thi) : "l"(at));
        float part = tlo + thi;
        if (rank == 0) part += xg;

        {   // pack 2 partials -> b64 message to peer's warp-w mbar
            float pnext = __shfl_down_sync(0xFFFFFFFFu, part, 1);
            if ((j & 1) == 0) {
                ull pk;
                asm("mov.b64 %0, {%1,%2};" : "=l"(pk) : "f"(part), "f"(pnext));
                unsigned dst = rm_pbuf + (((unsigned)(t & 1) << 9) + j) * 4u;
                asm volatile(
                    "st.async.shared::cluster.mbarrier::complete_tx::bytes.b64 [%0], %1, [%2];"
                    :: "r"(dst), "l"(pk), "r"(rm_mbar + (unsigned)(w << 3)) : "memory");
            }
        }

        MBWAIT(my_mbar, (unsigned)(t & 1));   // wait only for my warp's 128 B

        float g = part + pbuf[t & 1][j];
        float targ = sel_tanh ? g : 0.5f * g;
        float th   = tanh_hw(targ);
        float act  = sel_tanh ? th : fmaf(0.5f, th, 0.5f);
        a_s[j] = act;
        __syncthreads();

        if (j < 128) {
            float ai = a_s[j], af = a_s[128 + j], ag = a_s[256 + j], ao = a_s[384 + j];
            c = fmaf(af, c, ai * ag);
            h_s[j] = ao * tanh_hw(c);
        }
        __syncthreads();
    }

    if (rank == 0 && j < 128) {
        out[(size_t)b * HID + j] = h_s[j];                        // h  [1,64,128]
        out[(size_t)BATCH * HID + (size_t)b * HID + j] = c;       // c  [1,64,128]
    }

    asm volatile("barrier.cluster.arrive.aligned;" ::: "memory");
    asm volatile("barrier.cluster.wait.aligned;"   ::: "memory");
}

// ---------------------------------------------------------------------------
extern "C" void kernel_launch(void* const* d_in, const int* in_sizes, int n_in,
                              void* d_out, int out_size)
{
    const int*   tokens = (const int*)  d_in[0];
    const float* emb    = (const float*)d_in[1];
    const float* W_ih   = (const float*)d_in[2];
    const float* W_hh   = (const float*)d_in[3];
    const float* b_ih   = (const float*)d_in[4];
    const float* b_hh   = (const float*)d_in[5];
    float* out = (float*)d_out;

    cudaFuncSetAttribute(proj_mma_kernel,
                         cudaFuncAttributeMaxDynamicSharedMemorySize, SM_PROJ);

    const int ntot = NE4 + NW4 + GATES;
    split_kernel<<<(ntot + 255) / 256, 256>>>(emb, W_ih, b_ih, b_hh);

    dim3 g1((VOCAB + 127) / 128, GATES / 128);   // 393 x 4
    proj_mma_kernel<<<g1, 256, SM_PROJ>>>();

    lstm_kernel<<<BATCH * 2, 512>>>(tokens, W_hh, out);
}